// round 17
// baseline (speedup 1.0000x reference)
#include <cuda_runtime.h>
#include <cuda_bf16.h>
#include <math_constants.h>

#define BB 4
#define KK 8192
#define THREADS 256
#define RM 8                  // rows per thread -> 2048 rows per block
#define NSPLIT 64
#define TN (KK / NSPLIT)      // 128 targets per block = single tile
#define RBLOCKS 128
#define RTHREADS 256

// Per-point min distance, COMPLEMENT-encoded: e = ~bits(d), d >= 0.
// min(d) == max(e); e > 0 always, so zero-initialized globals are the "+inf"
// sentinel (no init kernel). reduce_kernel resets slots to 0 for graph replay.
__device__ unsigned int g_enc[2][BB * KK];
__device__ float g_part[3][RBLOCKS];
__device__ unsigned int g_done;   // zero-init; reset by last reduce block

// dir=0: owned=pred, other=target (min_p2t). dir=1: swapped.
// CLEAN SCALAR inner loop: per (j,r) exactly 3 FFMA + 1 FMNMX, no pack/unpack
// MOVs (the packed variant's ~25% issue-slot bookkeeping tax). RM=8 amortizes
// the per-j LDS.128 to 0.125 slots/pair. Issue floor ~4.4 slots/pair.
__global__ void __launch_bounds__(THREADS, 4)
chamfer_min_kernel(const float* __restrict__ pred, const float* __restrict__ target) {
    const int dir = blockIdx.z;
    const float* __restrict__ A  = dir ? target : pred;
    const float* __restrict__ Bp = dir ? pred : target;
    unsigned int* __restrict__ outenc = g_enc[dir];

    const int b      = blockIdx.y;
    const int tile   = blockIdx.x / NSPLIT;
    const int jsplit = blockIdx.x % NSPLIT;
    const int tid    = threadIdx.x;

    __shared__ float4 sh[TN];    // x, y, z, 0.5*|t|^2

    float nx[RM], ny[RM], nz[RM], p2[RM], m[RM];
    const int ibase = tile * (THREADS * RM) + tid;
#pragma unroll
    for (int r = 0; r < RM; r++) {
        const int i = ibase + r * THREADS;
        const float* p = A + ((size_t)b * KK + i) * 3;
        float x = p[0], y = p[1], z = p[2];
        nx[r] = -x; ny[r] = -y; nz[r] = -z;
        p2[r] = x * x + y * y + z * z;
        m[r] = CUDART_INF_F;
    }

    // Load this block's single target tile (threads 0..127).
    const int j0 = jsplit * TN;
    if (tid < TN) {
        const float* t = Bp + ((size_t)b * KK + j0 + tid) * 3;
        float x = t[0], y = t[1], z = t[2];
        sh[tid] = make_float4(x, y, z, 0.5f * (x * x + y * y + z * z));
    }
    __syncthreads();

    // v_j = 0.5*|t_j|^2 - dot(p, t_j); min over j.  d2 = p2 + 2*min(v).
#pragma unroll 4
    for (int j = 0; j < TN; j++) {
        const float4 t = sh[j];              // 1x LDS.128 broadcast, /8 rows
#pragma unroll
        for (int r = 0; r < RM; r++) {
            float v = fmaf(nz[r], t.z, t.w);
            v = fmaf(ny[r], t.y, v);
            v = fmaf(nx[r], t.x, v);
            m[r] = fminf(m[r], v);
        }
    }

#pragma unroll
    for (int r = 0; r < RM; r++) {
        float d2 = fmaf(2.0f, m[r], p2[r]);
        float d  = sqrtf(fmaxf(d2, 0.0f));
        atomicMax(&outenc[(size_t)b * KK + ibase + r * THREADS],
                  ~__float_as_uint(d));
    }
}

// Multi-block reduce + slot reset; last block (threadfence + counter) does the
// final deterministic combine. g_part values are fixed per replay, so the
// result does not depend on which block finishes last.
__global__ void __launch_bounds__(RTHREADS)
reduce_kernel(const float* __restrict__ mask, float* __restrict__ out) {
    float s0 = 0.f, s1 = 0.f, s2 = 0.f;
    for (int i = blockIdx.x * RTHREADS + threadIdx.x; i < BB * KK;
         i += RBLOCKS * RTHREADS) {
        float mk = mask[i];
        float d0 = __uint_as_float(~g_enc[0][i]);
        float d1 = __uint_as_float(~g_enc[1][i]);
        g_enc[0][i] = 0u;
        g_enc[1][i] = 0u;
        s0 = fmaf(d0, mk, s0);
        s1 = fmaf(d1, mk, s1);
        s2 += mk;
    }
    __shared__ float sh[3][RTHREADS];
    const int tid = threadIdx.x;
    sh[0][tid] = s0; sh[1][tid] = s1; sh[2][tid] = s2;
    __syncthreads();
    for (int off = RTHREADS / 2; off > 0; off >>= 1) {
        if (tid < off) {
            sh[0][tid] += sh[0][tid + off];
            sh[1][tid] += sh[1][tid + off];
            sh[2][tid] += sh[2][tid + off];
        }
        __syncthreads();
    }

    __shared__ unsigned int s_last;
    if (tid == 0) {
        g_part[0][blockIdx.x] = sh[0][0];
        g_part[1][blockIdx.x] = sh[1][0];
        g_part[2][blockIdx.x] = sh[2][0];
        __threadfence();
        s_last = (atomicAdd(&g_done, 1u) == RBLOCKS - 1u);
    }
    __syncthreads();

    if (s_last) {
        if (tid < RBLOCKS) {                 // 128 threads = 4 warps
            float a = g_part[0][tid], b = g_part[1][tid], c = g_part[2][tid];
#pragma unroll
            for (int off = 16; off > 0; off >>= 1) {
                a += __shfl_down_sync(0xFFFFFFFFu, a, off);
                b += __shfl_down_sync(0xFFFFFFFFu, b, off);
                c += __shfl_down_sync(0xFFFFFFFFu, c, off);
            }
            if ((tid & 31) == 0) {
                sh[0][tid >> 5] = a; sh[1][tid >> 5] = b; sh[2][tid >> 5] = c;
            }
        }
        __syncthreads();
        if (tid == 0) {
            float f0 = sh[0][0] + sh[0][1] + sh[0][2] + sh[0][3];
            float f1 = sh[1][0] + sh[1][1] + sh[1][2] + sh[1][3];
            float f2 = sh[2][0] + sh[2][1] + sh[2][2] + sh[2][3];
            out[0] = (f0 + f1) / (2.0f * (f2 + 1e-8f));
            g_done = 0u;                     // reset for next graph replay
        }
    }
}

extern "C" void kernel_launch(void* const* d_in, const int* in_sizes, int n_in,
                              void* d_out, int out_size) {
    const float* pred   = (const float*)d_in[0];
    const float* target = (const float*)d_in[1];
    const float* mask   = (const float*)d_in[2];
    float* out = (float*)d_out;

    // tiles(4) * NSPLIT(64) = 256;  256 x 4 x 2 = 2048 blocks
    dim3 grid(KK / (THREADS * RM) * NSPLIT, BB, 2);
    chamfer_min_kernel<<<grid, THREADS>>>(pred, target);

    reduce_kernel<<<RBLOCKS, RTHREADS>>>(mask, out);
}